// round 8
// baseline (speedup 1.0000x reference)
#include <cuda_runtime.h>
#include <cstdint>

#define CRF_B 1024
#define CRF_S 512
#define CRF_T 64

__device__ float g_partial[CRF_B];
__device__ unsigned int g_count = 0;

__device__ __forceinline__ float ex2f(float x) {
    float y; asm("ex2.approx.ftz.f32 %0, %1;" : "=f"(y) : "f"(x)); return y;
}
__device__ __forceinline__ float lg2f(float x) {
    float y; asm("lg2.approx.f32 %0, %1;" : "=f"(y) : "f"(x)); return y;
}
__device__ __forceinline__ unsigned long long fma2(unsigned long long a,
                                                   unsigned long long b,
                                                   unsigned long long c) {
    unsigned long long d;
    asm("fma.rn.f32x2 %0, %1, %2, %3;" : "=l"(d) : "l"(a), "l"(b), "l"(c));
    return d;
}
__device__ __forceinline__ unsigned long long add2(unsigned long long a,
                                                   unsigned long long b) {
    unsigned long long d;
    asm("add.rn.f32x2 %0, %1, %2;" : "=l"(d) : "l"(a), "l"(b));
    return d;
}
__device__ __forceinline__ unsigned long long mul2(unsigned long long a,
                                                   unsigned long long b) {
    unsigned long long d;
    asm("mul.rn.f32x2 %0, %1, %2;" : "=l"(d) : "l"(a), "l"(b));
    return d;
}
__device__ __forceinline__ unsigned long long pack2(float lo, float hi) {
    unsigned long long d;
    asm("mov.b64 %0, {%1, %2};" : "=l"(d) : "f"(lo), "f"(hi));
    return d;
}
__device__ __forceinline__ void unpack2(float& lo, float& hi, unsigned long long v) {
    asm("mov.b64 {%0, %1}, %2;" : "=f"(lo), "=f"(hi) : "l"(v));
}

// ONE WARP per batch element. Thread `lane` owns states (lane, lane+32),
// packed into the two f32x2 lanes. No __syncthreads anywhere in the scan:
// a single warp executes shared-memory ops in program order; __syncwarp()
// is only a compiler/ordering fence. Scaled linear-domain forward recurrence
// with exact power-of-2 renormalization computed off the critical chain.
__global__ void __launch_bounds__(32) crf_scan_kernel(
    const float* __restrict__ inputs,        // [B, S, T]
    const float* __restrict__ trans,         // [T, T]
    const unsigned char* __restrict__ masks, // [B, S]
    const int* __restrict__ tags,            // [B, S]
    float* __restrict__ out, int out_size)
{
    const int b = blockIdx.x;
    const int lane = threadIdx.x;
    const float L = 1.4426950408889634f;  // log2(e)

    // p_dup[i] = (p_i, p_i) packed — lane-duplicated for direct FMA2 use.
    __shared__ __align__(16) unsigned long long p_dup[CRF_T];
    __shared__ unsigned char mask_sh[CRF_S];

    const float* xb = inputs + (size_t)b * CRF_S * CRF_T;
    const int* tg = tags + (size_t)b * CRF_S;
    const unsigned char* mk = masks + (size_t)b * CRF_S;

    for (int s = lane; s < CRF_S; s += 32) mask_sh[s] = mk[s];
    __syncwarp();

    // unary + binary partial sums (strided over s, fixed order per lane)
    float ub = 0.f;
    for (int s = lane; s < CRF_S; s += 32) {
        if (!mask_sh[s]) {
            int ts = tg[s];
            ub += xb[s * CRF_T + ts];
            if (s >= 1) ub += trans[tg[s - 1] * CRF_T + ts];
        }
    }

    // E2[i] = ( e^trans[i][lane], e^trans[i][lane+32] )
    unsigned long long E2[CRF_T];
#pragma unroll
    for (int i = 0; i < CRF_T; i++) {
        float ea = ex2f(L * trans[i * CRF_T + lane]);
        float eb = ex2f(L * trans[i * CRF_T + lane + 32]);
        E2[i] = pack2(ea, eb);
    }

    // Init: stored p = 2^(L*x0 - A), A = L*x0[0]; running base-2 scale Kacc.
    float A = L * xb[0];
    float pa = ex2f(fmaf(L, xb[lane], -A));
    float pb = ex2f(fmaf(L, xb[lane + 32], -A));
    float Kacc = A;
    p_dup[lane] = pack2(pa, pa);
    p_dup[lane + 32] = pack2(pb, pb);
    __syncwarp();

    // x pipeline: xf = 2^(L*x_t) ready at step t; raw prefetch one ahead.
    float xfa = ex2f(L * xb[1 * CRF_T + lane]);
    float xfb = ex2f(L * xb[1 * CRF_T + lane + 32]);
    float xra = xb[2 * CRF_T + lane];
    float xrb = xb[2 * CRF_T + lane + 32];

#pragma unroll 1
    for (int t = 1; t < CRF_S; t++) {
        // ---- independent work first ----
        int i2 = (t + 2 < CRF_S) ? (t + 2) : (CRF_S - 1);
        float nra = xb[i2 * CRF_T + lane];
        float nrb = xb[i2 * CRF_T + lane + 32];
        float xfa_n = ex2f(L * xra);
        float xfb_n = ex2f(L * xrb);
        unsigned char m = mask_sh[t];

        // exact 2^-K renorm factor from previous p0 (off the FMA chain)
        float p0 = reinterpret_cast<const float*>(p_dup)[0];
        int K = ((__float_as_int(p0) >> 23) & 0xFF) - 127;
        float scale = __int_as_float((127 - K) << 23);
        unsigned long long comb = pack2(xfa * scale, xfb * scale);

        // ---- packed dot: both columns at once, 64 FMA2, 8 chains ----
        const ulonglong2* pq = reinterpret_cast<const ulonglong2*>(p_dup);
        unsigned long long acc[8];
#pragma unroll
        for (int c = 0; c < 8; c++) acc[c] = 0ull;
#pragma unroll
        for (int i = 0; i < 32; i++) {
            ulonglong2 q = pq[i];
            acc[i & 7] = fma2(q.x, E2[2 * i], acc[i & 7]);
            acc[i & 7] = fma2(q.y, E2[2 * i + 1], acc[i & 7]);
        }
        unsigned long long b0 = add2(acc[0], acc[1]);
        unsigned long long b1 = add2(acc[2], acc[3]);
        unsigned long long b2 = add2(acc[4], acc[5]);
        unsigned long long b3 = add2(acc[6], acc[7]);
        unsigned long long ss = add2(add2(b0, b1), add2(b2, b3));  // (ssum_a, ssum_b)

        unsigned long long pn = mul2(ss, comb);
        float pna, pnb; unpack2(pna, pnb, pn);
        if (!m) { pa = pna; pb = pnb; Kacc += (float)K; }
        p_dup[lane] = pack2(pa, pa);
        p_dup[lane + 32] = pack2(pb, pb);

        xfa = xfa_n; xfb = xfb_n; xra = nra; xrb = nrb;
        __syncwarp();
    }

    // log_norm = ( lg2( sum p_final ) + Kacc ) / L  — butterfly reduce (deterministic)
    float tot = pa + pb;
#pragma unroll
    for (int o = 16; o > 0; o >>= 1) tot += __shfl_xor_sync(0xFFFFFFFFu, tot, o);
    float log_norm = (lg2f(tot) + Kacc) / L;

    float ubt = ub;
#pragma unroll
    for (int o = 16; o > 0; o >>= 1) ubt += __shfl_xor_sync(0xFFFFFFFFu, ubt, o);

    unsigned int flag = 0;
    if (lane == 0) {
        g_partial[b] = -(ubt - log_norm);
        __threadfence();
        unsigned int v = atomicAdd(&g_count, 1u);
        flag = (v == CRF_B - 1) ? 1u : 0u;
    }
    flag = __shfl_sync(0xFFFFFFFFu, flag, 0);

    // Last CTA: deterministic final reduction + transitions passthrough
    if (flag) {
        __threadfence();
        float s = 0.f;
        for (int i = lane; i < CRF_B; i += 32) s += g_partial[i];  // fixed order
#pragma unroll
        for (int o = 16; o > 0; o >>= 1) s += __shfl_xor_sync(0xFFFFFFFFu, s, o);
        if (lane == 0) {
            out[0] = s / (float)CRF_B;
            g_count = 0;   // reset for graph replay
        }
        for (int i = lane; i < CRF_T * CRF_T && (1 + i) < out_size; i += 32)
            out[1 + i] = trans[i];
    }
}

extern "C" void kernel_launch(void* const* d_in, const int* in_sizes, int n_in,
                              void* d_out, int out_size)
{
    const float* inputs = (const float*)d_in[0];
    const float* trans  = (const float*)d_in[1];
    const unsigned char* masks = (const unsigned char*)d_in[2];
    const int* tags = (const int*)d_in[3];
    float* out = (float*)d_out;

    crf_scan_kernel<<<CRF_B, 32>>>(inputs, trans, masks, tags, out, out_size);
}

// round 9
// speedup vs baseline: 1.5494x; 1.5494x over previous
#include <cuda_runtime.h>
#include <cstdint>

#define CRF_B 1024
#define CRF_S 512
#define CRF_T 64
#define CRF_M 255   // forward covers t in [0,255]; backward covers t in [511,256]

// Static device scratch (no allocation)
__device__ float g_mid[2][CRF_B][CRF_T];   // [0]=fwd b-vec, [1]=bwd c-vec (base-2 logs)
__device__ float g_ub[CRF_B];              // unary+binary sum per batch
__device__ float g_partial[CRF_B];         // -log_likelihood per batch
__device__ unsigned int g_done[CRF_B];     // per-batch arrival counter (0-init)
__device__ unsigned int g_count = 0;       // global combine counter

__device__ __forceinline__ float ex2f(float x) {
    float y; asm("ex2.approx.ftz.f32 %0, %1;" : "=f"(y) : "f"(x)); return y;
}
__device__ __forceinline__ float lg2f(float x) {
    float y; asm("lg2.approx.f32 %0, %1;" : "=f"(y) : "f"(x)); return y;
}

// grid = (B, 2). blockIdx.y==0: forward half (+ unary/binary). ==1: backward half.
// 64 threads per CTA; thread j owns state j. Log-domain (base-2) recurrence with
// thread-0 anchor, exactly the R1 step structure.
__global__ void __launch_bounds__(CRF_T) crf_scan_kernel(
    const float* __restrict__ inputs,        // [B, S, T]
    const float* __restrict__ trans,         // [T, T]
    const unsigned char* __restrict__ masks, // [B, S]
    const int* __restrict__ tags,            // [B, S]
    float* __restrict__ out, int out_size)
{
    const int b = blockIdx.x;
    const int dir = blockIdx.y;
    const int j = threadIdx.x;
    const float L = 1.4426950408889634f;  // log2(e)

    __shared__ __align__(16) float p_sh[CRF_T];
    __shared__ float Msh;
    __shared__ float red[CRF_T];
    __shared__ unsigned char mask_sh[CRF_S];
    __shared__ unsigned int flag_sh;

    const float* xb = inputs + (size_t)b * CRF_S * CRF_T;
    const unsigned char* mk = masks + (size_t)b * CRF_S;

    for (int s = j; s < CRF_S; s += CRF_T) mask_sh[s] = mk[s];
    __syncthreads();

    float vj;  // this CTA's final base-2 log vector element (b_j or c_j)

    if (dir == 0) {
        // ---------------- forward half: t = 1 .. CRF_M ----------------
        const int* tg = tags + (size_t)b * CRF_S;

        // unary + binary partial sums over the FULL sequence (fwd CTA only)
        float ub = 0.f;
        for (int s = j; s < CRF_S; s += CRF_T) {
            if (!mask_sh[s]) {
                int ts = tg[s];
                ub += xb[s * CRF_T + ts];
                if (s >= 1) ub += trans[tg[s - 1] * CRF_T + ts];
            }
        }

        // E[i] = e^{trans[i][j]}  (column j, register-resident)
        float E[CRF_T];
#pragma unroll
        for (int i = 0; i < CRF_T; i++)
            E[i] = ex2f(L * trans[i * CRF_T + j]);

        float bj = L * xb[j];
        if (j == 0) Msh = bj;
        __syncthreads();

        float xnext = xb[CRF_T + j];

#pragma unroll 1
        for (int t = 1; t <= CRF_M; t++) {
            float M = Msh;
            p_sh[j] = ex2f(bj - M);
            float xt = xnext;
            unsigned char m = mask_sh[t];
            __syncthreads();
            if (t < CRF_M) xnext = xb[(t + 1) * CRF_T + j];

            float s0 = 0.f, s1 = 0.f, s2 = 0.f, s3 = 0.f;
            const float4* p4 = reinterpret_cast<const float4*>(p_sh);
#pragma unroll
            for (int i = 0; i < CRF_T / 4; i++) {
                float4 p = p4[i];
                s0 = fmaf(p.x, E[4 * i + 0], s0);
                s1 = fmaf(p.y, E[4 * i + 1], s1);
                s2 = fmaf(p.z, E[4 * i + 2], s2);
                s3 = fmaf(p.w, E[4 * i + 3], s3);
            }
            float ssum = (s0 + s1) + (s2 + s3);

            float bn = fmaf(xt, L, M + lg2f(ssum));
            if (!m) bj = bn;
            if (j == 0) Msh = bj;
            __syncthreads();
        }
        vj = bj;

        // stash unary+binary sum
        red[j] = ub;
        __syncthreads();
        if (j == 0) {
            float su = 0.f;
            for (int i = 0; i < CRF_T; i++) su += red[i];
            g_ub[b] = su;
        }
    } else {
        // ---------------- backward half: t = S-1 .. CRF_M+1 ----------------
        // r recurrence: c'_i = M + lg2( sum_j E[i][j] * 2^{L*x_tj + c_j - M} )
        // Er = row i... here thread j owns r-component j, needs E ROW j.
        float Er[CRF_T];
#pragma unroll
        for (int i = 0; i < CRF_T; i++)
            Er[i] = ex2f(L * trans[j * CRF_T + i]);   // E[j][i]

        float cj = 0.f;          // r = 1
        if (j == 0) Msh = 0.f;
        __syncthreads();

        float xnext = xb[(CRF_S - 1) * CRF_T + j];

#pragma unroll 1
        for (int t = CRF_S - 1; t > CRF_M; t--) {
            float M = Msh;
            float xt = xnext;
            unsigned char m = mask_sh[t];
            p_sh[j] = ex2f(fmaf(L, xt, cj - M));   // u_j = 2^{L x_tj + c_j - M}
            __syncthreads();
            if (t > CRF_M + 1) xnext = xb[(t - 1) * CRF_T + j];

            float s0 = 0.f, s1 = 0.f, s2 = 0.f, s3 = 0.f;
            const float4* p4 = reinterpret_cast<const float4*>(p_sh);
#pragma unroll
            for (int i = 0; i < CRF_T / 4; i++) {
                float4 p = p4[i];
                s0 = fmaf(p.x, Er[4 * i + 0], s0);
                s1 = fmaf(p.y, Er[4 * i + 1], s1);
                s2 = fmaf(p.z, Er[4 * i + 2], s2);
                s3 = fmaf(p.w, Er[4 * i + 3], s3);
            }
            float ssum = (s0 + s1) + (s2 + s3);

            float cn = M + lg2f(ssum);
            if (!m) cj = cn;
            if (j == 0) Msh = cj;
            __syncthreads();
        }
        vj = cj;
    }

    // publish half-result, then second arriver combines
    g_mid[dir][b][j] = vj;
    __threadfence();
    __syncthreads();
    if (j == 0) {
        unsigned int v = atomicAdd(&g_done[b], 1u);
        flag_sh = v;   // 1 => we arrived second
    }
    __syncthreads();

    if (flag_sh == 1u) {
        __threadfence();  // acquire the other half's writes
        float v = g_mid[0][b][j] + g_mid[1][b][j];
        red[j] = v;
        __syncthreads();
        float a0 = red[0];
        red[j] = ex2f(v - a0);
        __syncthreads();
        unsigned int gflag = 0;
        if (j == 0) {
            float sp = 0.f;
            for (int i = 0; i < CRF_T; i++) sp += red[i];
            float log_norm = (a0 + lg2f(sp)) / L;
            g_partial[b] = -(g_ub[b] - log_norm);
            g_done[b] = 0;            // reset for next graph replay
            __threadfence();
            unsigned int c = atomicAdd(&g_count, 1u);
            gflag = (c == CRF_B - 1) ? 1u : 0u;
            flag_sh = gflag + 2u;     // 3 => we are the global last
        }
        __syncthreads();

        if (flag_sh == 3u) {
            __threadfence();
            float s = 0.f;
            for (int i = j; i < CRF_B; i += CRF_T) s += g_partial[i];  // fixed order
            red[j] = s;
            __syncthreads();
            if (j == 0) {
                float tot = 0.f;
                for (int i = 0; i < CRF_T; i++) tot += red[i];
                out[0] = tot / (float)CRF_B;
                g_count = 0;          // reset for next graph replay
            }
            for (int i = j; i < CRF_T * CRF_T && (1 + i) < out_size; i += CRF_T)
                out[1 + i] = trans[i];
        }
    }
}

extern "C" void kernel_launch(void* const* d_in, const int* in_sizes, int n_in,
                              void* d_out, int out_size)
{
    const float* inputs = (const float*)d_in[0];
    const float* trans  = (const float*)d_in[1];
    const unsigned char* masks = (const unsigned char*)d_in[2];
    const int* tags = (const int*)d_in[3];
    float* out = (float*)d_out;

    dim3 grid(CRF_B, 2);
    crf_scan_kernel<<<grid, CRF_T>>>(inputs, trans, masks, tags, out, out_size);
}